// round 10
// baseline (speedup 1.0000x reference)
#include <cuda_runtime.h>
#include <cuda_bf16.h>
#include <math.h>
#include <stdint.h>

constexpr int B   = 128;
constexpr int L   = 128;
constexpr int D   = 300;
constexpr int MD  = 50;
constexpr int GIN = 350;
constexpr int GINP= 352;
constexpr int HD  = 256;
constexpr int G3  = 768;
constexpr int H   = 512;
constexpr int R   = 128;
constexpr int T   = 4;
constexpr int NK  = 4;
constexpr int ML  = B * L;

// ---- static scratch ----
__device__ __align__(16) __nv_bfloat16 d_xh[ML * GINP];
__device__ __align__(16) __nv_bfloat16 d_Wph[2 * G3 * GINP];
__device__ float d_gi[2 * (size_t)ML * G3];
__device__ float d_ctx[(size_t)ML * H];
__device__ float d_wtab[ML];
__device__ float d_Wc[16 * H];
__device__ float d_fk[NK * ML * T];
__device__ float d_sp[NK * ML];
__device__ float d_spsum[NK * B];
__device__ float d_tbeff[NK * T];
__device__ float d_scores[B * 3];

__device__ __forceinline__ float lse4(float v0, float v1, float v2, float v3) {
    float mx = fmaxf(fmaxf(v0, v1), fmaxf(v2, v3));
    return mx + logf(expf(v0 - mx) + expf(v1 - mx) + expf(v2 - mx) + expf(v3 - mx));
}
__device__ __forceinline__ float tf32r(float x) {
    uint32_t u; asm("cvt.rna.tf32.f32 %0, %1;" : "=r"(u) : "f"(x));
    return __uint_as_float(u);
}
__device__ __forceinline__ float tanha(float x) {
    float r; asm("tanh.approx.f32 %0, %1;" : "=f"(r) : "f"(x)); return r;
}
__device__ __forceinline__ float sigma(float x) {
    return fmaf(0.5f, tanha(0.5f * x), 0.5f);
}
__device__ __forceinline__ void mma8(float* c, const uint32_t* a, const uint32_t* b) {
    asm("mma.sync.aligned.m16n8k8.row.col.f32.tf32.tf32.f32 "
        "{%0,%1,%2,%3},{%4,%5,%6,%7},{%8,%9},{%0,%1,%2,%3};"
        : "+f"(c[0]), "+f"(c[1]), "+f"(c[2]), "+f"(c[3])
        : "r"(a[0]), "r"(a[1]), "r"(a[2]), "r"(a[3]), "r"(b[0]), "r"(b[1]));
}
__device__ __forceinline__ void mma16(float* c, const uint32_t* a, const uint32_t* b) {
    asm("mma.sync.aligned.m16n8k16.row.col.f32.bf16.bf16.f32 "
        "{%0,%1,%2,%3},{%4,%5,%6,%7},{%8,%9},{%0,%1,%2,%3};"
        : "+f"(c[0]), "+f"(c[1]), "+f"(c[2]), "+f"(c[3])
        : "r"(a[0]), "r"(a[1]), "r"(a[2]), "r"(a[3]), "r"(b[0]), "r"(b[1]));
}

// ---- prep_all ----
constexpr int NB_X = ML, NB_W = 2 * G3, NB_MAIN = NB_X + NB_W + 1;
constexpr int NB_Z = 2048;
constexpr size_t CTX4 = (size_t)ML * H / 4;

__global__ void prep_all(const float* __restrict__ sents, const float* __restrict__ mtab,
                         const int* __restrict__ masks, const int* __restrict__ lens,
                         const float* __restrict__ Wf, const float* __restrict__ Wb) {
    const int bid = blockIdx.x;
    if (bid < NB_X) {
        const int row = bid;
        const int msk = masks[row];
        for (int k = threadIdx.x; k < GINP; k += blockDim.x) {
            float v;
            if (k < D)        v = sents[(size_t)row * D + k];
            else if (k < GIN) v = mtab[msk * MD + (k - D)];
            else              v = 0.f;
            d_xh[(size_t)row * GINP + k] = __float2bfloat16(v);
        }
    } else if (bid < NB_X + NB_W) {
        const int q = bid - NB_X;
        const int dd = q / G3, g = q % G3;
        const float* W = dd ? Wb : Wf;
        for (int k = threadIdx.x; k < GINP; k += blockDim.x)
            d_Wph[((size_t)dd * G3 + g) * GINP + k] =
                __float2bfloat16((k < GIN) ? W[(size_t)g * GIN + k] : 0.f);
    } else if (bid == NB_X + NB_W) {
        const int b = threadIdx.x;
        if (b >= B) return;
        int begin = 0, tnum = 0; bool found = false;
        for (int j = 0; j < L; j++) {
            int m = masks[b * L + j];
            tnum += m;
            if (!found && m == 1) { begin = j; found = true; }
        }
        const int len = lens[b];
        const float lf = (float)len;
        for (int j = 0; j < L; j++) {
            float w = (j < begin) ? (1.f - (float)(begin - j) / lf) : 0.f;
            if (masks[b * L + j] == 1) w = 1.f;
            if (j > begin + tnum) w = 1.f - (float)(j - begin) / lf;
            if (j > len) w = 0.f;
            d_wtab[b * L + j] = w;
        }
    } else {
        const int z = bid - NB_MAIN;
        float4 zz = {0.f, 0.f, 0.f, 0.f};
        for (size_t i = (size_t)z * 128 + threadIdx.x; i < CTX4; i += (size_t)NB_Z * 128)
            ((float4*)d_ctx)[i] = zz;
    }
}

// ---- prep_small ----
__global__ void prep_small(const float* __restrict__ hW, const float* __restrict__ tW,
                           const float* __restrict__ hb, const float* __restrict__ tb) {
    if (blockIdx.x < 32) {
        const int idx = blockIdx.x * 256 + threadIdx.x;
        const int kb = idx >> 11, tt = (idx >> 9) & 3, h = idx & 511;
        float s = 0.f;
        for (int r = 0; r < R; r++)
            s += tW[(kb * T + tt) * R + r] * hW[((size_t)kb * R + r) * H + h];
        d_Wc[idx] = s;
    } else {
        const int i = threadIdx.x;
        if (i < NK * T) {
            const int kb = i >> 2;
            float s = tb[i];
            for (int r = 0; r < R; r++) s += hb[kb * R + r] * tW[i * R + r];
            d_tbeff[i] = s;
        }
    }
}

// ---- GEMM 1 (bf16 m16n8k16) ----
__global__ void __launch_bounds__(256) gemm_gi_bf16(const float* __restrict__ bihf,
                                                    const float* __restrict__ bihb) {
    __shared__ __align__(16) uint32_t a_s[128 * 12];
    __shared__ __align__(16) uint32_t b_s[128 * 12];
    const int tid = threadIdx.x;
    const int lane = tid & 31, warp = tid >> 5;
    const int n0 = blockIdx.x * 128;
    const int l  = blockIdx.y;
    const int dir = blockIdx.z;
    const int wm = (warp & 1) * 64, wn = (warp >> 1) * 32;
    const int lrow = tid >> 1, lhalf = tid & 1;

    float acc[4][4][4];
#pragma unroll
    for (int i = 0; i < 4; i++)
#pragma unroll
        for (int j = 0; j < 4; j++)
#pragma unroll
            for (int q = 0; q < 4; q++) acc[i][j][q] = 0.f;

    const int kb = lane & 3, rq = lane >> 2;
    for (int k0 = 0; k0 < GINP; k0 += 16) {
        uint4 va = *(const uint4*)(d_xh + ((size_t)lrow * L + l) * GINP + k0 + lhalf * 8);
        uint4 vb = *(const uint4*)(d_Wph + ((size_t)dir * G3 + n0 + lrow) * GINP + k0 + lhalf * 8);
        *(uint4*)&a_s[lrow * 12 + lhalf * 4] = va;
        *(uint4*)&b_s[lrow * 12 + lhalf * 4] = vb;
        __syncthreads();
        uint32_t af[4][4], bf[4][2];
#pragma unroll
        for (int i = 0; i < 4; i++) {
            const int r0 = wm + i * 16 + rq;
            af[i][0] = a_s[r0 * 12 + kb];
            af[i][1] = a_s[(r0 + 8) * 12 + kb];
            af[i][2] = a_s[r0 * 12 + kb + 4];
            af[i][3] = a_s[(r0 + 8) * 12 + kb + 4];
        }
#pragma unroll
        for (int j = 0; j < 4; j++) {
            const int nn = wn + j * 8 + rq;
            bf[j][0] = b_s[nn * 12 + kb];
            bf[j][1] = b_s[nn * 12 + kb + 4];
        }
#pragma unroll
        for (int i = 0; i < 4; i++)
#pragma unroll
            for (int j = 0; j < 4; j++) mma16(acc[i][j], af[i], bf[j]);
        __syncthreads();
    }
    const float* bih = dir ? bihb : bihf;
    float* C = d_gi + (size_t)dir * ML * G3 + (size_t)l * B * G3;
#pragma unroll
    for (int i = 0; i < 4; i++) {
        const int rb = wm + i * 16 + rq;
#pragma unroll
        for (int j = 0; j < 4; j++) {
            const int nn = n0 + wn + j * 8 + 2 * kb;
            const float b0 = bih[nn], b1 = bih[nn + 1];
            float2 v0 = {acc[i][j][0] + b0, acc[i][j][1] + b1};
            float2 v1 = {acc[i][j][2] + b0, acc[i][j][3] + b1};
            *(float2*)(C + (size_t)rb * G3 + nn) = v0;
            *(float2*)(C + (size_t)(rb + 8) * G3 + nn) = v1;
        }
    }
}

// ---- gru_v6: 8-CTA cluster per (dir,bg); h exchanged via DSMEM, no gmem h ----
// bx: gs = bx&7 (cluster rank), bg = (bx>>3)&7, dir = bx>>6.
__global__ void __cluster_dims__(8, 1, 1) __launch_bounds__(256, 1)
gru_v6(const int* __restrict__ lens,
       const float* __restrict__ Whhf, const float* __restrict__ Whhb,
       const float* __restrict__ bhhf, const float* __restrict__ bhhb) {
    extern __shared__ float sm[];
    float* w_s  = sm;                        // [96][260]
    float* a0   = sm + 96 * 260;             // [16][260] step buf 0
    float* a1   = a0 + 16 * 260;             // [16][260] step buf 1
    float* red  = a1 + 16 * 260;             // [128][13]
    int*   len_s = (int*)(red + 128 * 13);   // [16]

    const int tid = threadIdx.x;
    const int bx = blockIdx.x;
    const int gs  = bx & 7;
    const int bg  = (bx >> 3) & 7;
    const int dir = bx >> 6;
    const int b0  = bg * 16;
    const float* Whh = dir ? Whhb : Whhf;
    const float* bhh = dir ? bhhb : bhhf;

    for (int q = tid; q < 96 * 64; q += 256) {
        const int n = q >> 6, c4 = (q & 63) * 4;
        const int grow = (n >> 5) * HD + gs * 32 + (n & 31);
        float4 v = *(const float4*)(Whh + (size_t)grow * HD + c4);
        v.x = tf32r(v.x); v.y = tf32r(v.y); v.z = tf32r(v.z); v.w = tf32r(v.w);
        *(float4*)&w_s[n * 260 + c4] = v;
    }
    if (tid < 16) len_s[tid] = lens[b0 + tid];
    __syncthreads();

    const int lane = tid & 31, warp = tid >> 5;
    const int wlo = warp & 3, kh = warp >> 2;
    const int r0 = lane >> 2, cb = lane & 3;
    const int ul = wlo * 8 + 2 * cb;
    const int ug = gs * 32 + ul;
    const float bR0 = bhh[ug],        bR1 = bhh[ug + 1];
    const float bZ0 = bhh[256 + ug],  bZ1 = bhh[256 + ug + 1];
    const float bN0 = bhh[512 + ug],  bN1 = bhh[512 + ug + 1];
    const float* gi = d_gi + (size_t)dir * ML * G3;

    float* abuf[2] = {a0, a1};
    uint32_t a_u32[2];
    a_u32[0] = (uint32_t)__cvta_generic_to_shared(a0);
    a_u32[1] = (uint32_t)__cvta_generic_to_shared(a1);

    const int lenA = len_s[r0], lenB = len_s[r0 + 8];
    float2 hnA = {0.f, 0.f}, hnB = {0.f, 0.f};   // register-carried h for own units

    for (int t = 0; t < L; t++) {
        const int cur = t & 1, nxt = cur ^ 1;
        const float* a_s = abuf[cur];

        // gi prefetch (warps 0-3)
        float2 gr[2], gz[2], gn[2];
        int posv[2]; bool act[2];
        if (warp < 4) {
            const int lenv[2] = {lenA, lenB};
#pragma unroll
            for (int s = 0; s < 2; s++) {
                act[s] = (t < lenv[s]);
                posv[s] = dir ? (lenv[s] - 1 - t) : t;
                if (act[s]) {
                    const float* gp = gi + ((size_t)posv[s] * B + (b0 + r0 + 8 * s)) * G3;
                    gr[s] = *(const float2*)(gp + ug);
                    gz[s] = *(const float2*)(gp + 256 + ug);
                    gn[s] = *(const float2*)(gp + 512 + ug);
                }
            }
        }

        float acc[3][4];
#pragma unroll
        for (int j = 0; j < 3; j++)
#pragma unroll
            for (int q = 0; q < 4; q++) acc[j][q] = 0.f;

        if (t > 0) {
#pragma unroll 4
            for (int kk = 0; kk < 16; kk++) {
                const int cc = kh * 128 + kk * 8 + cb;
                uint32_t a[4];
                a[0] = __float_as_uint(a_s[r0 * 260 + cc]);
                a[1] = __float_as_uint(a_s[(r0 + 8) * 260 + cc]);
                a[2] = __float_as_uint(a_s[r0 * 260 + cc + 4]);
                a[3] = __float_as_uint(a_s[(r0 + 8) * 260 + cc + 4]);
#pragma unroll
                for (int j = 0; j < 3; j++) {
                    const int nn = j * 32 + wlo * 8 + r0;
                    uint32_t bb[2];
                    bb[0] = __float_as_uint(w_s[nn * 260 + cc]);
                    bb[1] = __float_as_uint(w_s[nn * 260 + cc + 4]);
                    mma8(acc[j], a, bb);
                }
            }
        }

        // k-half reduce
        if (warp >= 4) {
            const int idx = (warp - 4) * 32 + lane;
#pragma unroll
            for (int j = 0; j < 3; j++)
#pragma unroll
                for (int q = 0; q < 4; q++) red[idx * 13 + j * 4 + q] = acc[j][q];
        }
        __syncthreads();

        if (warp < 4) {
            const int idx = warp * 32 + lane;
#pragma unroll
            for (int j = 0; j < 3; j++)
#pragma unroll
                for (int q = 0; q < 4; q++) acc[j][q] += red[idx * 13 + j * 4 + q];

            // elementwise; h carried in registers
            float2* hc[2] = {&hnA, &hnB};
#pragma unroll
            for (int s = 0; s < 2; s++) {
                const float2 hp = *hc[s];
                float2 hn = hp;
                if (act[s]) {
                    const int b = b0 + r0 + 8 * s;
                    const float rrx = sigma(gr[s].x + acc[0][2 * s]     + bR0);
                    const float rry = sigma(gr[s].y + acc[0][2 * s + 1] + bR1);
                    const float zzx = sigma(gz[s].x + acc[1][2 * s]     + bZ0);
                    const float zzy = sigma(gz[s].y + acc[1][2 * s + 1] + bZ1);
                    const float nnx = tanha(gn[s].x + rrx * (acc[2][2 * s]     + bN0));
                    const float nny = tanha(gn[s].y + rry * (acc[2][2 * s + 1] + bN1));
                    hn.x = (1.f - zzx) * nnx + zzx * hp.x;
                    hn.y = (1.f - zzy) * nny + zzy * hp.y;
                    const int pos = posv[s];
                    const float wt = d_wtab[b * L + pos];
                    float2 cv = {hn.x * wt, hn.y * wt};
                    *(float2*)(d_ctx + ((size_t)b * L + pos) * H + dir * HD + ug) = cv;
                }
                *hc[s] = hn;
            }

            // broadcast tf32(hn) into every cluster CTA's next buffer
            const float tAx = tf32r(hnA.x), tAy = tf32r(hnA.y);
            const float tBx = tf32r(hnB.x), tBy = tf32r(hnB.y);
            const uint32_t offA = a_u32[nxt] + (uint32_t)(r0 * 260 + ug) * 4u;
            const uint32_t offB = a_u32[nxt] + (uint32_t)((r0 + 8) * 260 + ug) * 4u;
#pragma unroll
            for (int rk = 0; rk < 8; rk++) {
                uint32_t pa, pb;
                asm("mapa.shared::cluster.u32 %0, %1, %2;" : "=r"(pa) : "r"(offA), "r"(rk));
                asm volatile("st.shared::cluster.v2.f32 [%0], {%1, %2};"
                             :: "r"(pa), "f"(tAx), "f"(tAy) : "memory");
                asm("mapa.shared::cluster.u32 %0, %1, %2;" : "=r"(pb) : "r"(offB), "r"(rk));
                asm volatile("st.shared::cluster.v2.f32 [%0], {%1, %2};"
                             :: "r"(pb), "f"(tBx), "f"(tBy) : "memory");
            }
        }

        // cluster barrier: releases DSMEM stores, separates step buffers
        asm volatile("barrier.cluster.arrive.aligned;" ::: "memory");
        asm volatile("barrier.cluster.wait.aligned;" ::: "memory");
    }
}

// ---- fk2 (tiled) ----
__global__ void __launch_bounds__(256) fk2() {
    extern __shared__ float fsm[];
    float* wc_s = fsm;
    float* ct_s = fsm + 16 * 516;
    const int tid = threadIdx.x;
    const int m0 = blockIdx.x * 128;

    for (int q = tid; q < 2048; q += 256) {
        const int o = q >> 7, c4 = (q & 127) * 4;
        *(float4*)&wc_s[o * 516 + c4] = *(const float4*)(d_Wc + (size_t)o * H + c4);
    }
    __syncthreads();

    const int ml = tid >> 4, o = tid & 15;
    const float tbe = d_tbeff[o];
    for (int c = 0; c < 8; c++) {
        for (int q = tid; q < 2048; q += 256) {
            const int r = q >> 7, c4 = (q & 127) * 4;
            *(float4*)&ct_s[r * 520 + c4] =
                *(const float4*)(d_ctx + (size_t)(m0 + c * 16 + r) * H + c4);
        }
        __syncthreads();
        float acc = 0.f;
#pragma unroll 8
        for (int k4 = 0; k4 < 128; k4++) {
            float4 cv = *(const float4*)&ct_s[ml * 520 + k4 * 4];
            float4 wv = *(const float4*)&wc_s[o * 516 + k4 * 4];
            acc += cv.x * wv.x + cv.y * wv.y + cv.z * wv.z + cv.w * wv.w;
        }
        const int m = m0 + c * 16 + ml;
        d_fk[((size_t)(o >> 2) * ML + m) * T + (o & 3)] = acc + tbe;
        __syncthreads();
    }
}

// ---- CRF marginals ----
__global__ void __launch_bounds__(32) crf_kernel(const int* __restrict__ lens,
                                                 const float* __restrict__ trans) {
    __shared__ float al_s[8 * 516];
    const int tid = threadIdx.x;
    const int tag = tid & 3;
    const int ci  = tid >> 2;
    const int chain = blockIdx.x * 8 + ci;
    const int kb = chain >> 7;
    const int b  = chain & 127;
    const int len = lens[b];
    const unsigned fm = 0xffffffffu;
    const int base = tid & ~3;
    float* al = al_s + ci * 516;

    float tcol[4], trow[4];
#pragma unroll
    for (int i = 0; i < 4; i++) {
        tcol[i] = trans[kb * 16 + i * 4 + tag];
        trow[i] = trans[kb * 16 + tag * 4 + i];
    }
    const float* f = d_fk + ((size_t)kb * ML + (size_t)b * L) * T;

    float alpha = f[tag];
    al[tag] = alpha;
    for (int l = 1; l < L; l++) {
        float a0 = __shfl_sync(fm, alpha, base + 0);
        float a1 = __shfl_sync(fm, alpha, base + 1);
        float a2 = __shfl_sync(fm, alpha, base + 2);
        float a3 = __shfl_sync(fm, alpha, base + 3);
        float na = lse4(a0 + tcol[0], a1 + tcol[1], a2 + tcol[2], a3 + tcol[3]) + f[l * T + tag];
        if (l < len) alpha = na;
        al[l * 4 + tag] = alpha;
    }
    float beta = 0.f, ssum = 0.f;
    float* sp = d_sp + (size_t)(kb * B + b) * L;
    for (int l = L - 1; l >= 0; l--) {
        float v = al[l * 4 + tag] + beta;
        float v0 = __shfl_sync(fm, v, base + 0);
        float v1 = __shfl_sync(fm, v, base + 1);
        float v2 = __shfl_sync(fm, v, base + 2);
        float v3 = __shfl_sync(fm, v, base + 3);
        float p1 = expf(v1 - lse4(v0, v1, v2, v3));
        float spl = (l < len) ? p1 : 0.f;
        ssum += spl;
        if (tag == 0) sp[l] = spl;
        if (l >= 1) {
            float fb = f[l * T + tag] + beta;
            float c0 = __shfl_sync(fm, fb, base + 0);
            float c1 = __shfl_sync(fm, fb, base + 1);
            float c2 = __shfl_sync(fm, fb, base + 2);
            float c3 = __shfl_sync(fm, fb, base + 3);
            float nb2 = lse4(trow[0] + c0, trow[1] + c1, trow[2] + c2, trow[3] + c3);
            if (l < len) beta = nb2;
        }
    }
    if (tag == 0) d_spsum[kb * B + b] = ssum;
}

// ---- pooling + classifier fused ----
__global__ void __launch_bounds__(512) poolcls(const float* __restrict__ lW,
                                               const float* __restrict__ lb) {
    const int b = blockIdx.x, tid = threadIdx.x;
    __shared__ float spn[512];
    __shared__ float red[3][512];
    {
        const int kb = tid >> 7, l = tid & 127;
        spn[tid] = d_sp[(size_t)(kb * B + b) * L + l] / d_spsum[kb * B + b];
    }
    __syncthreads();
    float a0 = 0.f, a1 = 0.f, a2 = 0.f, a3 = 0.f;
    const float* c = d_ctx + (size_t)b * L * H + tid;
    for (int l = 0; l < 128; l++) {
        float cv = c[(size_t)l * H];
        a0 += spn[l] * cv; a1 += spn[128 + l] * cv;
        a2 += spn[256 + l] * cv; a3 += spn[384 + l] * cv;
    }
    float p0 = 0.f, p1 = 0.f, p2 = 0.f, s;
    s = fmaxf(a0, 0.f); p0 += s * lW[tid];        p1 += s * lW[2048 + tid];        p2 += s * lW[4096 + tid];
    s = fmaxf(a1, 0.f); p0 += s * lW[512 + tid];  p1 += s * lW[2560 + tid];        p2 += s * lW[4608 + tid];
    s = fmaxf(a2, 0.f); p0 += s * lW[1024 + tid]; p1 += s * lW[3072 + tid];        p2 += s * lW[5120 + tid];
    s = fmaxf(a3, 0.f); p0 += s * lW[1536 + tid]; p1 += s * lW[3584 + tid];        p2 += s * lW[5632 + tid];
    red[0][tid] = p0; red[1][tid] = p1; red[2][tid] = p2;
    __syncthreads();
    for (int off = 256; off > 0; off >>= 1) {
        if (tid < off) {
            red[0][tid] += red[0][tid + off];
            red[1][tid] += red[1][tid + off];
            red[2][tid] += red[2][tid + off];
        }
        __syncthreads();
    }
    if (tid < 3) d_scores[b * 3 + tid] = red[tid][0] + lb[tid];
}

__global__ void __launch_bounds__(128) loss_kernel(const int* __restrict__ labels,
                                                   float* __restrict__ out) {
    __shared__ float red[128];
    const int b = threadIdx.x;
    float s0 = d_scores[b * 3], s1 = d_scores[b * 3 + 1], s2 = d_scores[b * 3 + 2];
    float m = fmaxf(s0, fmaxf(s1, s2));
    float lse = m + logf(expf(s0 - m) + expf(s1 - m) + expf(s2 - m));
    int lab = labels[b];
    float sl = (lab == 0) ? s0 : ((lab == 1) ? s1 : s2);
    red[b] = lse - sl;
    __syncthreads();
    for (int off = 64; off > 0; off >>= 1) {
        if (b < off) red[b] += red[b + off];
        __syncthreads();
    }
    if (b == 0) out[0] = red[0] / (float)B;
}

extern "C" void kernel_launch(void* const* d_in, const int* in_sizes, int n_in,
                              void* d_out, int out_size) {
    (void)in_sizes; (void)n_in; (void)out_size;
    const float* sents = (const float*)d_in[0];
    const float* mtab  = (const float*)d_in[1];
    const float* gWihf = (const float*)d_in[2];
    const float* gWhhf = (const float*)d_in[3];
    const float* gbihf = (const float*)d_in[4];
    const float* gbhhf = (const float*)d_in[5];
    const float* gWihb = (const float*)d_in[6];
    const float* gWhhb = (const float*)d_in[7];
    const float* gbihb = (const float*)d_in[8];
    const float* gbhhb = (const float*)d_in[9];
    const float* hW    = (const float*)d_in[10];
    const float* hb    = (const float*)d_in[11];
    const float* tW    = (const float*)d_in[12];
    const float* tb    = (const float*)d_in[13];
    const float* trans = (const float*)d_in[14];
    const float* lW    = (const float*)d_in[15];
    const float* lb    = (const float*)d_in[16];
    const int* masks   = (const int*)d_in[17];
    const int* lens    = (const int*)d_in[18];
    const int* labels  = (const int*)d_in[19];
    float* out = (float*)d_out;

    const int smem_gru = (96 * 260 + 2 * 16 * 260 + 128 * 13) * 4 + 16 * 4;
    cudaFuncSetAttribute(gru_v6, cudaFuncAttributeMaxDynamicSharedMemorySize, smem_gru);
    const int smem_fk = (16 * 516 + 16 * 520) * 4;
    cudaFuncSetAttribute(fk2, cudaFuncAttributeMaxDynamicSharedMemorySize, smem_fk);

    prep_all<<<NB_MAIN + NB_Z, 128>>>(sents, mtab, masks, lens, gWihf, gWihb);  // 1
    prep_small<<<33, 256>>>(hW, tW, hb, tb);                                     // 2
    gemm_gi_bf16<<<dim3(6, 128, 2), 256>>>(gbihf, gbihb);                        // 3
    gru_v6<<<128, 256, smem_gru>>>(lens, gWhhf, gWhhb, gbhhf, gbhhb);            // 4 <- ncu
    fk2<<<128, 256, smem_fk>>>();                                                // 5
    crf_kernel<<<64, 32>>>(lens, trans);                                         // 6
    poolcls<<<B, 512>>>(lW, lb);                                                 // 7
    loss_kernel<<<1, 128>>>(labels, out);                                        // 8
}

// round 11
// speedup vs baseline: 1.6918x; 1.6918x over previous
#include <cuda_runtime.h>
#include <cuda_bf16.h>
#include <math.h>
#include <stdint.h>

constexpr int B   = 128;
constexpr int L   = 128;
constexpr int D   = 300;
constexpr int MD  = 50;
constexpr int GIN = 350;
constexpr int GINP= 352;
constexpr int HD  = 256;
constexpr int G3  = 768;
constexpr int H   = 512;
constexpr int R   = 128;
constexpr int T   = 4;
constexpr int NK  = 4;
constexpr int ML  = B * L;

// ---- static scratch ----
__device__ __align__(16) __nv_bfloat16 d_xh[ML * GINP];
__device__ __align__(16) __nv_bfloat16 d_Wph[2 * G3 * GINP];
__device__ float d_gi[2 * (size_t)ML * G3];
__device__ float d_h[2 * 2 * B * HD];
__device__ float d_ctx[(size_t)ML * H];
__device__ float d_wtab[ML];
__device__ float d_Wc[16 * H];
__device__ float d_fk[NK * ML * T];
__device__ float d_sp[NK * ML];
__device__ float d_spsum[NK * B];
__device__ float d_tbeff[NK * T];
__device__ float d_scores[B * 3];
__device__ int   d_flags[2 * 8 * 128 * 8];   // [dir][bg][t][gs]

__device__ __forceinline__ float lse4(float v0, float v1, float v2, float v3) {
    float mx = fmaxf(fmaxf(v0, v1), fmaxf(v2, v3));
    return mx + logf(expf(v0 - mx) + expf(v1 - mx) + expf(v2 - mx) + expf(v3 - mx));
}
__device__ __forceinline__ float tf32r(float x) {
    uint32_t u; asm("cvt.rna.tf32.f32 %0, %1;" : "=r"(u) : "f"(x));
    return __uint_as_float(u);
}
__device__ __forceinline__ float tanha(float x) {
    float r; asm("tanh.approx.f32 %0, %1;" : "=f"(r) : "f"(x)); return r;
}
__device__ __forceinline__ float sigma(float x) {
    return fmaf(0.5f, tanha(0.5f * x), 0.5f);
}
__device__ __forceinline__ void mma8(float* c, const uint32_t* a, const uint32_t* b) {
    asm("mma.sync.aligned.m16n8k8.row.col.f32.tf32.tf32.f32 "
        "{%0,%1,%2,%3},{%4,%5,%6,%7},{%8,%9},{%0,%1,%2,%3};"
        : "+f"(c[0]), "+f"(c[1]), "+f"(c[2]), "+f"(c[3])
        : "r"(a[0]), "r"(a[1]), "r"(a[2]), "r"(a[3]), "r"(b[0]), "r"(b[1]));
}
__device__ __forceinline__ void mma16(float* c, const uint32_t* a, const uint32_t* b) {
    asm("mma.sync.aligned.m16n8k16.row.col.f32.bf16.bf16.f32 "
        "{%0,%1,%2,%3},{%4,%5,%6,%7},{%8,%9},{%0,%1,%2,%3};"
        : "+f"(c[0]), "+f"(c[1]), "+f"(c[2]), "+f"(c[3])
        : "r"(a[0]), "r"(a[1]), "r"(a[2]), "r"(a[3]), "r"(b[0]), "r"(b[1]));
}

// ---- prep_all ----
constexpr int NB_X = ML, NB_W = 2 * G3, NB_MAIN = NB_X + NB_W + 1;
constexpr int NB_Z = 2048;
constexpr size_t CTX4 = (size_t)ML * H / 4;
constexpr size_t FL4  = sizeof(d_flags) / 16;
constexpr size_t ZT   = CTX4 + FL4;

__global__ void prep_all(const float* __restrict__ sents, const float* __restrict__ mtab,
                         const int* __restrict__ masks, const int* __restrict__ lens,
                         const float* __restrict__ Wf, const float* __restrict__ Wb) {
    const int bid = blockIdx.x;
    if (bid < NB_X) {
        const int row = bid;
        const int msk = masks[row];
        for (int k = threadIdx.x; k < GINP; k += blockDim.x) {
            float v;
            if (k < D)        v = sents[(size_t)row * D + k];
            else if (k < GIN) v = mtab[msk * MD + (k - D)];
            else              v = 0.f;
            d_xh[(size_t)row * GINP + k] = __float2bfloat16(v);
        }
    } else if (bid < NB_X + NB_W) {
        const int q = bid - NB_X;
        const int dd = q / G3, g = q % G3;
        const float* W = dd ? Wb : Wf;
        for (int k = threadIdx.x; k < GINP; k += blockDim.x)
            d_Wph[((size_t)dd * G3 + g) * GINP + k] =
                __float2bfloat16((k < GIN) ? W[(size_t)g * GIN + k] : 0.f);
    } else if (bid == NB_X + NB_W) {
        const int b = threadIdx.x;
        if (b >= B) return;
        int begin = 0, tnum = 0; bool found = false;
        for (int j = 0; j < L; j++) {
            int m = masks[b * L + j];
            tnum += m;
            if (!found && m == 1) { begin = j; found = true; }
        }
        const int len = lens[b];
        const float lf = (float)len;
        for (int j = 0; j < L; j++) {
            float w = (j < begin) ? (1.f - (float)(begin - j) / lf) : 0.f;
            if (masks[b * L + j] == 1) w = 1.f;
            if (j > begin + tnum) w = 1.f - (float)(j - begin) / lf;
            if (j > len) w = 0.f;
            d_wtab[b * L + j] = w;
        }
    } else {
        const int z = bid - NB_MAIN;
        float4 zz = {0.f, 0.f, 0.f, 0.f};
        for (size_t i = (size_t)z * 128 + threadIdx.x; i < ZT; i += (size_t)NB_Z * 128) {
            if (i < CTX4) ((float4*)d_ctx)[i] = zz;
            else          ((float4*)d_flags)[i - CTX4] = zz;
        }
    }
}

// ---- prep_small ----
__global__ void prep_small(const float* __restrict__ hW, const float* __restrict__ tW,
                           const float* __restrict__ hb, const float* __restrict__ tb) {
    if (blockIdx.x < 32) {
        const int idx = blockIdx.x * 256 + threadIdx.x;
        const int kb = idx >> 11, tt = (idx >> 9) & 3, h = idx & 511;
        float s = 0.f;
        for (int r = 0; r < R; r++)
            s += tW[(kb * T + tt) * R + r] * hW[((size_t)kb * R + r) * H + h];
        d_Wc[idx] = s;
    } else {
        const int i = threadIdx.x;
        if (i < NK * T) {
            const int kb = i >> 2;
            float s = tb[i];
            for (int r = 0; r < R; r++) s += hb[kb * R + r] * tW[i * R + r];
            d_tbeff[i] = s;
        }
    }
}

// ---- GEMM 1 (bf16 m16n8k16, 32-k per phase) ----
__global__ void __launch_bounds__(256) gemm_gi_bf16(const float* __restrict__ bihf,
                                                    const float* __restrict__ bihb) {
    __shared__ __align__(16) uint32_t a_s[128 * 28];   // chunk0 cols 0-7, chunk1 cols 12-19
    __shared__ __align__(16) uint32_t b_s[128 * 28];
    const int tid = threadIdx.x;
    const int lane = tid & 31, warp = tid >> 5;
    const int n0 = blockIdx.x * 128;
    const int l  = blockIdx.y;
    const int dir = blockIdx.z;
    const int wm = (warp & 1) * 64, wn = (warp >> 1) * 32;
    const int lrow = tid >> 1, lhalf = tid & 1;

    float acc[4][4][4];
#pragma unroll
    for (int i = 0; i < 4; i++)
#pragma unroll
        for (int j = 0; j < 4; j++)
#pragma unroll
            for (int q = 0; q < 4; q++) acc[i][j][q] = 0.f;

    const int kb = lane & 3, rq = lane >> 2;
    const __nv_bfloat16* xa = d_xh + (size_t)lrow * L * GINP + l * GINP;
    const __nv_bfloat16* wb = d_Wph + ((size_t)dir * G3 + n0 + lrow) * GINP;

    for (int k0 = 0; k0 < GINP; k0 += 32) {
        *(uint4*)&a_s[lrow * 28 + lhalf * 4]      = *(const uint4*)(xa + k0 + lhalf * 8);
        *(uint4*)&a_s[lrow * 28 + 12 + lhalf * 4] = *(const uint4*)(xa + k0 + 16 + lhalf * 8);
        *(uint4*)&b_s[lrow * 28 + lhalf * 4]      = *(const uint4*)(wb + k0 + lhalf * 8);
        *(uint4*)&b_s[lrow * 28 + 12 + lhalf * 4] = *(const uint4*)(wb + k0 + 16 + lhalf * 8);
        __syncthreads();
#pragma unroll
        for (int c = 0; c < 2; c++) {
            const int kof = c * 12 + kb;
            uint32_t af[4][4], bf[4][2];
#pragma unroll
            for (int i = 0; i < 4; i++) {
                const int r0 = wm + i * 16 + rq;
                af[i][0] = a_s[r0 * 28 + kof];
                af[i][1] = a_s[(r0 + 8) * 28 + kof];
                af[i][2] = a_s[r0 * 28 + kof + 4];
                af[i][3] = a_s[(r0 + 8) * 28 + kof + 4];
            }
#pragma unroll
            for (int j = 0; j < 4; j++) {
                const int nn = wn + j * 8 + rq;
                bf[j][0] = b_s[nn * 28 + kof];
                bf[j][1] = b_s[nn * 28 + kof + 4];
            }
#pragma unroll
            for (int i = 0; i < 4; i++)
#pragma unroll
                for (int j = 0; j < 4; j++) mma16(acc[i][j], af[i], bf[j]);
        }
        __syncthreads();
    }
    const float* bih = dir ? bihb : bihf;
    float* C = d_gi + (size_t)dir * ML * G3 + (size_t)l * B * G3;
#pragma unroll
    for (int i = 0; i < 4; i++) {
        const int rb = wm + i * 16 + rq;
#pragma unroll
        for (int j = 0; j < 4; j++) {
            const int nn = n0 + wn + j * 8 + 2 * kb;
            const float b0 = bih[nn], b1 = bih[nn + 1];
            float2 v0 = {acc[i][j][0] + b0, acc[i][j][1] + b1};
            float2 v1 = {acc[i][j][2] + b0, acc[i][j][3] + b1};
            *(float2*)(C + (size_t)rb * G3 + nn) = v0;
            *(float2*)(C + (size_t)(rb + 8) * G3 + nn) = v1;
        }
    }
}

// ---- gru_v7: v4 dataflow + register h + smem wtab + deferred ctx stores ----
__global__ void __launch_bounds__(256, 1) gru_v7(const int* __restrict__ lens,
                                                 const float* __restrict__ Whhf,
                                                 const float* __restrict__ Whhb,
                                                 const float* __restrict__ bhhf,
                                                 const float* __restrict__ bhhb) {
    extern __shared__ float sm[];
    float* w_s   = sm;                       // [96][260]
    float* a_s   = sm + 96 * 260;            // [16][260]
    float* red   = a_s + 16 * 260;           // [128][13]
    float* wt_s  = red + 128 * 13;           // [16][128]
    int*   len_s = (int*)(wt_s + 16 * 128);  // [16]

    const int tid = threadIdx.x;
    const int bx = blockIdx.x;
    const int dir = bx >> 6;
    const int gs  = (bx >> 3) & 7;
    const int bg  = bx & 7;
    const int b0  = bg * 16;
    const float* Whh = dir ? Whhb : Whhf;
    const float* bhh = dir ? bhhb : bhhf;

    for (int q = tid; q < 96 * 64; q += 256) {
        const int n = q >> 6, c4 = (q & 63) * 4;
        const int grow = (n >> 5) * HD + gs * 32 + (n & 31);
        float4 v = *(const float4*)(Whh + (size_t)grow * HD + c4);
        v.x = tf32r(v.x); v.y = tf32r(v.y); v.z = tf32r(v.z); v.w = tf32r(v.w);
        *(float4*)&w_s[n * 260 + c4] = v;
    }
    for (int q = tid; q < 16 * 128 / 4; q += 256)
        *(float4*)&wt_s[q * 4] = *(const float4*)(d_wtab + b0 * L + q * 4);
    if (tid < 16) len_s[tid] = lens[b0 + tid];
    __syncthreads();

    const int lane = tid & 31, warp = tid >> 5;
    const int wlo = warp & 3, kh = warp >> 2;
    const int r0 = lane >> 2, cb = lane & 3;
    const int ul = wlo * 8 + 2 * cb;
    const int ug = gs * 32 + ul;
    const float bR0 = bhh[ug],        bR1 = bhh[ug + 1];
    const float bZ0 = bhh[256 + ug],  bZ1 = bhh[256 + ug + 1];
    const float bN0 = bhh[512 + ug],  bN1 = bhh[512 + ug + 1];
    const float* gi = d_gi + (size_t)dir * ML * G3;
    int* flg = d_flags + ((dir * 8 + bg) * 128) * 8;

    const int lenA = len_s[r0], lenB = len_s[r0 + 8];
    float2 hA = {0.f, 0.f}, hB = {0.f, 0.f};   // register h for own (row, unit-pair)

    for (int t = 0; t < L; t++) {
        const int buf = t & 1;
        const float* hbase = d_h + buf * (2 * B * HD) + dir * (B * HD);
        float* hout = d_h + (buf ^ 1) * (2 * B * HD) + dir * (B * HD);

        // gi prefetch (warps 0-3) — issued before the poll
        float2 gr[2], gz[2], gn[2];
        int posv[2]; bool act[2];
        if (warp < 4) {
            const int lenv[2] = {lenA, lenB};
#pragma unroll
            for (int s = 0; s < 2; s++) {
                act[s] = (t < lenv[s]);
                posv[s] = dir ? (lenv[s] - 1 - t) : t;
                if (act[s]) {
                    const float* gp = gi + ((size_t)posv[s] * B + (b0 + r0 + 8 * s)) * G3;
                    gr[s] = *(const float2*)(gp + ug);
                    gz[s] = *(const float2*)(gp + 256 + ug);
                    gn[s] = *(const float2*)(gp + 512 + ug);
                }
            }
        }

        float acc[3][4];
#pragma unroll
        for (int j = 0; j < 3; j++)
#pragma unroll
            for (int q = 0; q < 4; q++) acc[j][q] = 0.f;

        if (t > 0) {
            if (tid < 8) {
                int fv;
                do {
                    asm volatile("ld.acquire.gpu.global.b32 %0, [%1];"
                                 : "=r"(fv) : "l"(flg + (t - 1) * 8 + tid));
                } while (fv == 0);
            }
            __syncthreads();
#pragma unroll
            for (int i = 0; i < 2; i++) {
                const int q = tid + 256 * i;          // 0..511
                const int r = q >> 5;
                const int c8 = (q & 31) * 8;
                float4 v0 = __ldcg((const float4*)(hbase + (size_t)(b0 + r) * HD + c8));
                float4 v1 = __ldcg((const float4*)(hbase + (size_t)(b0 + r) * HD + c8 + 4));
                v0.x = tf32r(v0.x); v0.y = tf32r(v0.y); v0.z = tf32r(v0.z); v0.w = tf32r(v0.w);
                v1.x = tf32r(v1.x); v1.y = tf32r(v1.y); v1.z = tf32r(v1.z); v1.w = tf32r(v1.w);
                *(float4*)&a_s[r * 260 + c8] = v0;
                *(float4*)&a_s[r * 260 + c8 + 4] = v1;
            }
            __syncthreads();

#pragma unroll 4
            for (int kk = 0; kk < 16; kk++) {
                const int cc = kh * 128 + kk * 8 + cb;
                uint32_t a[4];
                a[0] = __float_as_uint(a_s[r0 * 260 + cc]);
                a[1] = __float_as_uint(a_s[(r0 + 8) * 260 + cc]);
                a[2] = __float_as_uint(a_s[r0 * 260 + cc + 4]);
                a[3] = __float_as_uint(a_s[(r0 + 8) * 260 + cc + 4]);
#pragma unroll
                for (int j = 0; j < 3; j++) {
                    const int nn = j * 32 + wlo * 8 + r0;
                    uint32_t bb[2];
                    bb[0] = __float_as_uint(w_s[nn * 260 + cc]);
                    bb[1] = __float_as_uint(w_s[nn * 260 + cc + 4]);
                    mma8(acc[j], a, bb);
                }
            }
        }

        // reduce k-halves
        if (warp >= 4) {
            const int idx = (warp - 4) * 32 + lane;
#pragma unroll
            for (int j = 0; j < 3; j++)
#pragma unroll
                for (int q = 0; q < 4; q++) red[idx * 13 + j * 4 + q] = acc[j][q];
        }
        __syncthreads();

        if (warp < 4) {
            const int idx = warp * 32 + lane;
#pragma unroll
            for (int j = 0; j < 3; j++)
#pragma unroll
                for (int q = 0; q < 4; q++) acc[j][q] += red[idx * 13 + j * 4 + q];

            float2* hc[2] = {&hA, &hB};
#pragma unroll
            for (int s = 0; s < 2; s++) {
                const float2 hp = *hc[s];
                float2 hn = hp;
                if (act[s]) {
                    const float rrx = sigma(gr[s].x + acc[0][2 * s]     + bR0);
                    const float rry = sigma(gr[s].y + acc[0][2 * s + 1] + bR1);
                    const float zzx = sigma(gz[s].x + acc[1][2 * s]     + bZ0);
                    const float zzy = sigma(gz[s].y + acc[1][2 * s + 1] + bZ1);
                    const float nnx = tanha(gn[s].x + rrx * (acc[2][2 * s]     + bN0));
                    const float nny = tanha(gn[s].y + rry * (acc[2][2 * s + 1] + bN1));
                    hn.x = (1.f - zzx) * nnx + zzx * hp.x;
                    hn.y = (1.f - zzy) * nny + zzy * hp.y;
                }
                *hc[s] = hn;
                const int b = b0 + r0 + 8 * s;
                *(float2*)(hout + (size_t)b * HD + ug) = hn;   // exchange store only
            }
        }

        __syncthreads();
        if (tid == 0) {
            __threadfence();
            *(volatile int*)(flg + t * 8 + gs) = 1;
        }

        // ctx stores AFTER the flag — off the dependency critical path
        if (warp < 4) {
            const float2 hv[2] = {hA, hB};
#pragma unroll
            for (int s = 0; s < 2; s++) {
                if (act[s]) {
                    const int r = r0 + 8 * s;
                    const int b = b0 + r;
                    const float wt = wt_s[r * 128 + posv[s]];
                    float2 cv = {hv[s].x * wt, hv[s].y * wt};
                    *(float2*)(d_ctx + ((size_t)b * L + posv[s]) * H + dir * HD + ug) = cv;
                }
            }
        }
    }
}

// ---- fk2 (tiled) ----
__global__ void __launch_bounds__(256) fk2() {
    extern __shared__ float fsm[];
    float* wc_s = fsm;
    float* ct_s = fsm + 16 * 516;
    const int tid = threadIdx.x;
    const int m0 = blockIdx.x * 128;

    for (int q = tid; q < 2048; q += 256) {
        const int o = q >> 7, c4 = (q & 127) * 4;
        *(float4*)&wc_s[o * 516 + c4] = *(const float4*)(d_Wc + (size_t)o * H + c4);
    }
    __syncthreads();

    const int ml = tid >> 4, o = tid & 15;
    const float tbe = d_tbeff[o];
    for (int c = 0; c < 8; c++) {
        for (int q = tid; q < 2048; q += 256) {
            const int r = q >> 7, c4 = (q & 127) * 4;
            *(float4*)&ct_s[r * 520 + c4] =
                *(const float4*)(d_ctx + (size_t)(m0 + c * 16 + r) * H + c4);
        }
        __syncthreads();
        float acc = 0.f;
#pragma unroll 8
        for (int k4 = 0; k4 < 128; k4++) {
            float4 cv = *(const float4*)&ct_s[ml * 520 + k4 * 4];
            float4 wv = *(const float4*)&wc_s[o * 516 + k4 * 4];
            acc += cv.x * wv.x + cv.y * wv.y + cv.z * wv.z + cv.w * wv.w;
        }
        const int m = m0 + c * 16 + ml;
        d_fk[((size_t)(o >> 2) * ML + m) * T + (o & 3)] = acc + tbe;
        __syncthreads();
    }
}

// ---- CRF marginals ----
__global__ void __launch_bounds__(32) crf_kernel(const int* __restrict__ lens,
                                                 const float* __restrict__ trans) {
    __shared__ float al_s[8 * 516];
    const int tid = threadIdx.x;
    const int tag = tid & 3;
    const int ci  = tid >> 2;
    const int chain = blockIdx.x * 8 + ci;
    const int kb = chain >> 7;
    const int b  = chain & 127;
    const int len = lens[b];
    const unsigned fm = 0xffffffffu;
    const int base = tid & ~3;
    float* al = al_s + ci * 516;

    float tcol[4], trow[4];
#pragma unroll
    for (int i = 0; i < 4; i++) {
        tcol[i] = trans[kb * 16 + i * 4 + tag];
        trow[i] = trans[kb * 16 + tag * 4 + i];
    }
    const float* f = d_fk + ((size_t)kb * ML + (size_t)b * L) * T;

    float alpha = f[tag];
    al[tag] = alpha;
    for (int l = 1; l < L; l++) {
        float a0 = __shfl_sync(fm, alpha, base + 0);
        float a1 = __shfl_sync(fm, alpha, base + 1);
        float a2 = __shfl_sync(fm, alpha, base + 2);
        float a3 = __shfl_sync(fm, alpha, base + 3);
        float na = lse4(a0 + tcol[0], a1 + tcol[1], a2 + tcol[2], a3 + tcol[3]) + f[l * T + tag];
        if (l < len) alpha = na;
        al[l * 4 + tag] = alpha;
    }
    float beta = 0.f, ssum = 0.f;
    float* sp = d_sp + (size_t)(kb * B + b) * L;
    for (int l = L - 1; l >= 0; l--) {
        float v = al[l * 4 + tag] + beta;
        float v0 = __shfl_sync(fm, v, base + 0);
        float v1 = __shfl_sync(fm, v, base + 1);
        float v2 = __shfl_sync(fm, v, base + 2);
        float v3 = __shfl_sync(fm, v, base + 3);
        float p1 = expf(v1 - lse4(v0, v1, v2, v3));
        float spl = (l < len) ? p1 : 0.f;
        ssum += spl;
        if (tag == 0) sp[l] = spl;
        if (l >= 1) {
            float fb = f[l * T + tag] + beta;
            float c0 = __shfl_sync(fm, fb, base + 0);
            float c1 = __shfl_sync(fm, fb, base + 1);
            float c2 = __shfl_sync(fm, fb, base + 2);
            float c3 = __shfl_sync(fm, fb, base + 3);
            float nb2 = lse4(trow[0] + c0, trow[1] + c1, trow[2] + c2, trow[3] + c3);
            if (l < len) beta = nb2;
        }
    }
    if (tag == 0) d_spsum[kb * B + b] = ssum;
}

// ---- pooling + classifier fused ----
__global__ void __launch_bounds__(512) poolcls(const float* __restrict__ lW,
                                               const float* __restrict__ lb) {
    const int b = blockIdx.x, tid = threadIdx.x;
    __shared__ float spn[512];
    __shared__ float red[3][512];
    {
        const int kb = tid >> 7, l = tid & 127;
        spn[tid] = d_sp[(size_t)(kb * B + b) * L + l] / d_spsum[kb * B + b];
    }
    __syncthreads();
    float a0 = 0.f, a1 = 0.f, a2 = 0.f, a3 = 0.f;
    const float* c = d_ctx + (size_t)b * L * H + tid;
    for (int l = 0; l < 128; l++) {
        float cv = c[(size_t)l * H];
        a0 += spn[l] * cv; a1 += spn[128 + l] * cv;
        a2 += spn[256 + l] * cv; a3 += spn[384 + l] * cv;
    }
    float p0 = 0.f, p1 = 0.f, p2 = 0.f, s;
    s = fmaxf(a0, 0.f); p0 += s * lW[tid];        p1 += s * lW[2048 + tid];        p2 += s * lW[4096 + tid];
    s = fmaxf(a1, 0.f); p0 += s * lW[512 + tid];  p1 += s * lW[2560 + tid];        p2 += s * lW[4608 + tid];
    s = fmaxf(a2, 0.f); p0 += s * lW[1024 + tid]; p1 += s * lW[3072 + tid];        p2 += s * lW[5120 + tid];
    s = fmaxf(a3, 0.f); p0 += s * lW[1536 + tid]; p1 += s * lW[3584 + tid];        p2 += s * lW[5632 + tid];
    red[0][tid] = p0; red[1][tid] = p1; red[2][tid] = p2;
    __syncthreads();
    for (int off = 256; off > 0; off >>= 1) {
        if (tid < off) {
            red[0][tid] += red[0][tid + off];
            red[1][tid] += red[1][tid + off];
            red[2][tid] += red[2][tid + off];
        }
        __syncthreads();
    }
    if (tid < 3) d_scores[b * 3 + tid] = red[tid][0] + lb[tid];
}

__global__ void __launch_bounds__(128) loss_kernel(const int* __restrict__ labels,
                                                   float* __restrict__ out) {
    __shared__ float red[128];
    const int b = threadIdx.x;
    float s0 = d_scores[b * 3], s1 = d_scores[b * 3 + 1], s2 = d_scores[b * 3 + 2];
    float m = fmaxf(s0, fmaxf(s1, s2));
    float lse = m + logf(expf(s0 - m) + expf(s1 - m) + expf(s2 - m));
    int lab = labels[b];
    float sl = (lab == 0) ? s0 : ((lab == 1) ? s1 : s2);
    red[b] = lse - sl;
    __syncthreads();
    for (int off = 64; off > 0; off >>= 1) {
        if (b < off) red[b] += red[b + off];
        __syncthreads();
    }
    if (b == 0) out[0] = red[0] / (float)B;
}

extern "C" void kernel_launch(void* const* d_in, const int* in_sizes, int n_in,
                              void* d_out, int out_size) {
    (void)in_sizes; (void)n_in; (void)out_size;
    const float* sents = (const float*)d_in[0];
    const float* mtab  = (const float*)d_in[1];
    const float* gWihf = (const float*)d_in[2];
    const float* gWhhf = (const float*)d_in[3];
    const float* gbihf = (const float*)d_in[4];
    const float* gbhhf = (const float*)d_in[5];
    const float* gWihb = (const float*)d_in[6];
    const float* gWhhb = (const float*)d_in[7];
    const float* gbihb = (const float*)d_in[8];
    const float* gbhhb = (const float*)d_in[9];
    const float* hW    = (const float*)d_in[10];
    const float* hb    = (const float*)d_in[11];
    const float* tW    = (const float*)d_in[12];
    const float* tb    = (const float*)d_in[13];
    const float* trans = (const float*)d_in[14];
    const float* lW    = (const float*)d_in[15];
    const float* lb    = (const float*)d_in[16];
    const int* masks   = (const int*)d_in[17];
    const int* lens    = (const int*)d_in[18];
    const int* labels  = (const int*)d_in[19];
    float* out = (float*)d_out;

    const int smem_gru = (96 * 260 + 16 * 260 + 128 * 13 + 16 * 128) * 4 + 16 * 4;
    cudaFuncSetAttribute(gru_v7, cudaFuncAttributeMaxDynamicSharedMemorySize, smem_gru);
    const int smem_fk = (16 * 516 + 16 * 520) * 4;
    cudaFuncSetAttribute(fk2, cudaFuncAttributeMaxDynamicSharedMemorySize, smem_fk);

    prep_all<<<NB_MAIN + NB_Z, 128>>>(sents, mtab, masks, lens, gWihf, gWihb);  // 1
    prep_small<<<33, 256>>>(hW, tW, hb, tb);                                     // 2
    gemm_gi_bf16<<<dim3(6, 128, 2), 256>>>(gbihf, gbihb);                        // 3
    gru_v7<<<128, 256, smem_gru>>>(lens, gWhhf, gWhhb, gbhhf, gbhhb);            // 4 <- ncu
    fk2<<<128, 256, smem_fk>>>();                                                // 5
    crf_kernel<<<64, 32>>>(lens, trans);                                         // 6
    poolcls<<<B, 512>>>(lW, lb);                                                 // 7
    loss_kernel<<<1, 128>>>(labels, out);                                        // 8
}

// round 13
// speedup vs baseline: 1.7521x; 1.0356x over previous
#include <cuda_runtime.h>
#include <cuda_bf16.h>
#include <math.h>
#include <stdint.h>

constexpr int B   = 128;
constexpr int L   = 128;
constexpr int D   = 300;
constexpr int MD  = 50;
constexpr int GIN = 350;
constexpr int GINP= 352;
constexpr int HD  = 256;
constexpr int G3  = 768;
constexpr int H   = 512;
constexpr int R   = 128;
constexpr int T   = 4;
constexpr int NK  = 4;
constexpr int ML  = B * L;

// ---- static scratch ----
__device__ __align__(16) __nv_bfloat16 d_xh[ML * GINP];
__device__ __align__(16) __nv_bfloat16 d_Wph[2 * G3 * GINP];
__device__ float d_gi[2 * (size_t)ML * G3];
__device__ float d_h[2 * 2 * B * HD];
__device__ float d_ctx[(size_t)ML * H];
__device__ float d_wtab[ML];
__device__ float d_Wc[16 * H];
__device__ float d_fk[NK * ML * T];
__device__ float d_sp[NK * ML];
__device__ float d_spsum[NK * B];
__device__ float d_tbeff[NK * T];
__device__ float d_scores[B * 3];
__device__ int   d_flags[2 * 8 * 128 * 8];   // [dir][bg][t][gs]

__device__ __forceinline__ float lse4(float v0, float v1, float v2, float v3) {
    float mx = fmaxf(fmaxf(v0, v1), fmaxf(v2, v3));
    return mx + logf(expf(v0 - mx) + expf(v1 - mx) + expf(v2 - mx) + expf(v3 - mx));
}
__device__ __forceinline__ float tf32r(float x) {
    uint32_t u; asm("cvt.rna.tf32.f32 %0, %1;" : "=r"(u) : "f"(x));
    return __uint_as_float(u);
}
__device__ __forceinline__ float tanha(float x) {
    float r; asm("tanh.approx.f32 %0, %1;" : "=f"(r) : "f"(x)); return r;
}
__device__ __forceinline__ float sigma(float x) {
    return fmaf(0.5f, tanha(0.5f * x), 0.5f);
}
__device__ __forceinline__ void mma8(float* c, const uint32_t* a, const uint32_t* b) {
    asm("mma.sync.aligned.m16n8k8.row.col.f32.tf32.tf32.f32 "
        "{%0,%1,%2,%3},{%4,%5,%6,%7},{%8,%9},{%0,%1,%2,%3};"
        : "+f"(c[0]), "+f"(c[1]), "+f"(c[2]), "+f"(c[3])
        : "r"(a[0]), "r"(a[1]), "r"(a[2]), "r"(a[3]), "r"(b[0]), "r"(b[1]));
}
__device__ __forceinline__ void mma16(float* c, const uint32_t* a, const uint32_t* b) {
    asm("mma.sync.aligned.m16n8k16.row.col.f32.bf16.bf16.f32 "
        "{%0,%1,%2,%3},{%4,%5,%6,%7},{%8,%9},{%0,%1,%2,%3};"
        : "+f"(c[0]), "+f"(c[1]), "+f"(c[2]), "+f"(c[3])
        : "r"(a[0]), "r"(a[1]), "r"(a[2]), "r"(a[3]), "r"(b[0]), "r"(b[1]));
}
__device__ __forceinline__ void ldsm4(uint32_t* r, uint32_t addr) {
    asm volatile("ldmatrix.sync.aligned.m8n8.x4.shared.b16 {%0,%1,%2,%3}, [%4];"
                 : "=r"(r[0]), "=r"(r[1]), "=r"(r[2]), "=r"(r[3]) : "r"(addr));
}
__device__ __forceinline__ void ldsm2(uint32_t* r, uint32_t addr) {
    asm volatile("ldmatrix.sync.aligned.m8n8.x2.shared.b16 {%0,%1}, [%2];"
                 : "=r"(r[0]), "=r"(r[1]) : "r"(addr));
}

// ---- prep_all ----
constexpr int NB_X = ML, NB_W = 2 * G3, NB_MAIN = NB_X + NB_W + 1;
constexpr int NB_Z = 2048;
constexpr size_t CTX4 = (size_t)ML * H / 4;
constexpr size_t FL4  = sizeof(d_flags) / 16;
constexpr size_t ZT   = CTX4 + FL4;

__global__ void prep_all(const float* __restrict__ sents, const float* __restrict__ mtab,
                         const int* __restrict__ masks, const int* __restrict__ lens,
                         const float* __restrict__ Wf, const float* __restrict__ Wb) {
    const int bid = blockIdx.x;
    if (bid < NB_X) {
        const int row = bid;
        const int msk = masks[row];
        for (int k = threadIdx.x; k < GINP; k += blockDim.x) {
            float v;
            if (k < D)        v = sents[(size_t)row * D + k];
            else if (k < GIN) v = mtab[msk * MD + (k - D)];
            else              v = 0.f;
            d_xh[(size_t)row * GINP + k] = __float2bfloat16(v);
        }
    } else if (bid < NB_X + NB_W) {
        const int q = bid - NB_X;
        const int dd = q / G3, g = q % G3;
        const float* W = dd ? Wb : Wf;
        for (int k = threadIdx.x; k < GINP; k += blockDim.x)
            d_Wph[((size_t)dd * G3 + g) * GINP + k] =
                __float2bfloat16((k < GIN) ? W[(size_t)g * GIN + k] : 0.f);
    } else if (bid == NB_X + NB_W) {
        const int b = threadIdx.x;
        if (b >= B) return;
        int begin = 0, tnum = 0; bool found = false;
        for (int j = 0; j < L; j++) {
            int m = masks[b * L + j];
            tnum += m;
            if (!found && m == 1) { begin = j; found = true; }
        }
        const int len = lens[b];
        const float lf = (float)len;
        for (int j = 0; j < L; j++) {
            float w = (j < begin) ? (1.f - (float)(begin - j) / lf) : 0.f;
            if (masks[b * L + j] == 1) w = 1.f;
            if (j > begin + tnum) w = 1.f - (float)(j - begin) / lf;
            if (j > len) w = 0.f;
            d_wtab[b * L + j] = w;
        }
    } else {
        const int z = bid - NB_MAIN;
        float4 zz = {0.f, 0.f, 0.f, 0.f};
        for (size_t i = (size_t)z * 128 + threadIdx.x; i < ZT; i += (size_t)NB_Z * 128) {
            if (i < CTX4) ((float4*)d_ctx)[i] = zz;
            else          ((float4*)d_flags)[i - CTX4] = zz;
        }
    }
}

// ---- prep_small ----
__global__ void prep_small(const float* __restrict__ hW, const float* __restrict__ tW,
                           const float* __restrict__ hb, const float* __restrict__ tb) {
    if (blockIdx.x < 32) {
        const int idx = blockIdx.x * 256 + threadIdx.x;
        const int kb = idx >> 11, tt = (idx >> 9) & 3, h = idx & 511;
        float s = 0.f;
        for (int r = 0; r < R; r++)
            s += tW[(kb * T + tt) * R + r] * hW[((size_t)kb * R + r) * H + h];
        d_Wc[idx] = s;
    } else {
        const int i = threadIdx.x;
        if (i < NK * T) {
            const int kb = i >> 2;
            float s = tb[i];
            for (int r = 0; r < R; r++) s += hb[kb * R + r] * tW[i * R + r];
            d_tbeff[i] = s;
        }
    }
}

__global__ void noop_k() {}

// ---- GEMM 1 (bf16 m16n8k16, ldmatrix fragment feed) ----
__global__ void __launch_bounds__(256) gemm_gi_bf16(const float* __restrict__ bihf,
                                                    const float* __restrict__ bihb) {
    __shared__ __align__(16) uint32_t a_s[128 * 28];   // chunk0 cols 0-7, chunk1 cols 12-19
    __shared__ __align__(16) uint32_t b_s[128 * 28];
    const int tid = threadIdx.x;
    const int lane = tid & 31, warp = tid >> 5;
    const int n0 = blockIdx.x * 128;
    const int l  = blockIdx.y;
    const int dir = blockIdx.z;
    const int wm = (warp & 1) * 64, wn = (warp >> 1) * 32;
    const int lrow = tid >> 1, lhalf = tid & 1;

    float acc[4][4][4];
#pragma unroll
    for (int i = 0; i < 4; i++)
#pragma unroll
        for (int j = 0; j < 4; j++)
#pragma unroll
            for (int q = 0; q < 4; q++) acc[i][j][q] = 0.f;

    const int kb = lane & 3, rq = lane >> 2;
    const __nv_bfloat16* xa = d_xh + (size_t)lrow * L * GINP + l * GINP;
    const __nv_bfloat16* wb = d_Wph + ((size_t)dir * G3 + n0 + lrow) * GINP;

    // precompute ldmatrix addresses (k0-invariant)
    const uint32_t a_base = (uint32_t)__cvta_generic_to_shared(a_s);
    const uint32_t b_base = (uint32_t)__cvta_generic_to_shared(b_s);
    uint32_t aaddr[4][2], baddr[4][2];
    {
        const int arow = (lane & 7) + ((lane >> 3) & 1) * 8;   // row within 16
        const int acol = (lane >> 4) * 4;                       // k-half select
#pragma unroll
        for (int i = 0; i < 4; i++)
#pragma unroll
            for (int c = 0; c < 2; c++)
                aaddr[i][c] = a_base + (uint32_t)(((wm + i * 16 + arow) * 28) + c * 12 + acol) * 4u;
        const int ll = lane & 15;
        const int brow = ll & 7;
        const int bcol = ((ll >> 3) & 1) * 4;
#pragma unroll
        for (int j = 0; j < 4; j++)
#pragma unroll
            for (int c = 0; c < 2; c++)
                baddr[j][c] = b_base + (uint32_t)(((wn + j * 8 + brow) * 28) + c * 12 + bcol) * 4u;
    }

    for (int k0 = 0; k0 < GINP; k0 += 32) {
        *(uint4*)&a_s[lrow * 28 + lhalf * 4]      = *(const uint4*)(xa + k0 + lhalf * 8);
        *(uint4*)&a_s[lrow * 28 + 12 + lhalf * 4] = *(const uint4*)(xa + k0 + 16 + lhalf * 8);
        *(uint4*)&b_s[lrow * 28 + lhalf * 4]      = *(const uint4*)(wb + k0 + lhalf * 8);
        *(uint4*)&b_s[lrow * 28 + 12 + lhalf * 4] = *(const uint4*)(wb + k0 + 16 + lhalf * 8);
        __syncthreads();
#pragma unroll
        for (int c = 0; c < 2; c++) {
            uint32_t af[4][4], bf[4][2];
#pragma unroll
            for (int i = 0; i < 4; i++) ldsm4(af[i], aaddr[i][c]);
#pragma unroll
            for (int j = 0; j < 4; j++) ldsm2(bf[j], baddr[j][c]);
#pragma unroll
            for (int i = 0; i < 4; i++)
#pragma unroll
                for (int j = 0; j < 4; j++) mma16(acc[i][j], af[i], bf[j]);
        }
        __syncthreads();
    }
    const float* bih = dir ? bihb : bihf;
    float* C = d_gi + (size_t)dir * ML * G3 + (size_t)l * B * G3;
#pragma unroll
    for (int i = 0; i < 4; i++) {
        const int rb = wm + i * 16 + rq;
#pragma unroll
        for (int j = 0; j < 4; j++) {
            const int nn = n0 + wn + j * 8 + 2 * kb;
            const float b0 = bih[nn], b1 = bih[nn + 1];
            float2 v0 = {acc[i][j][0] + b0, acc[i][j][1] + b1};
            float2 v1 = {acc[i][j][2] + b0, acc[i][j][3] + b1};
            *(float2*)(C + (size_t)rb * G3 + nn) = v0;
            *(float2*)(C + (size_t)(rb + 8) * G3 + nn) = v1;
        }
    }
}

// ---- gru_v7 (round-11, proven): tf32 mma, fp32 gi/h, register h, smem wtab ----
__global__ void __launch_bounds__(256, 1) gru_v7(const int* __restrict__ lens,
                                                 const float* __restrict__ Whhf,
                                                 const float* __restrict__ Whhb,
                                                 const float* __restrict__ bhhf,
                                                 const float* __restrict__ bhhb) {
    extern __shared__ float sm[];
    float* w_s   = sm;                       // [96][260]
    float* a_s   = sm + 96 * 260;            // [16][260]
    float* red   = a_s + 16 * 260;           // [128][13]
    float* wt_s  = red + 128 * 13;           // [16][128]
    int*   len_s = (int*)(wt_s + 16 * 128);  // [16]

    const int tid = threadIdx.x;
    const int bx = blockIdx.x;
    const int dir = bx >> 6;
    const int gs  = (bx >> 3) & 7;
    const int bg  = bx & 7;
    const int b0  = bg * 16;
    const float* Whh = dir ? Whhb : Whhf;
    const float* bhh = dir ? bhhb : bhhf;

    for (int q = tid; q < 96 * 64; q += 256) {
        const int n = q >> 6, c4 = (q & 63) * 4;
        const int grow = (n >> 5) * HD + gs * 32 + (n & 31);
        float4 v = *(const float4*)(Whh + (size_t)grow * HD + c4);
        v.x = tf32r(v.x); v.y = tf32r(v.y); v.z = tf32r(v.z); v.w = tf32r(v.w);
        *(float4*)&w_s[n * 260 + c4] = v;
    }
    for (int q = tid; q < 16 * 128 / 4; q += 256)
        *(float4*)&wt_s[q * 4] = *(const float4*)(d_wtab + b0 * L + q * 4);
    if (tid < 16) len_s[tid] = lens[b0 + tid];
    __syncthreads();

    const int lane = tid & 31, warp = tid >> 5;
    const int wlo = warp & 3, kh = warp >> 2;
    const int r0 = lane >> 2, cb = lane & 3;
    const int ul = wlo * 8 + 2 * cb;
    const int ug = gs * 32 + ul;
    const float bR0 = bhh[ug],        bR1 = bhh[ug + 1];
    const float bZ0 = bhh[256 + ug],  bZ1 = bhh[256 + ug + 1];
    const float bN0 = bhh[512 + ug],  bN1 = bhh[512 + ug + 1];
    const float* gi = d_gi + (size_t)dir * ML * G3;
    int* flg = d_flags + ((dir * 8 + bg) * 128) * 8;

    const int lenA = len_s[r0], lenB = len_s[r0 + 8];
    float2 hA = {0.f, 0.f}, hB = {0.f, 0.f};

    for (int t = 0; t < L; t++) {
        const int buf = t & 1;
        const float* hbase = d_h + buf * (2 * B * HD) + dir * (B * HD);
        float* hout = d_h + (buf ^ 1) * (2 * B * HD) + dir * (B * HD);

        float2 gr[2], gz[2], gn[2];
        int posv[2]; bool act[2];
        if (warp < 4) {
            const int lenv[2] = {lenA, lenB};
#pragma unroll
            for (int s = 0; s < 2; s++) {
                act[s] = (t < lenv[s]);
                posv[s] = dir ? (lenv[s] - 1 - t) : t;
                if (act[s]) {
                    const float* gp = gi + ((size_t)posv[s] * B + (b0 + r0 + 8 * s)) * G3;
                    gr[s] = *(const float2*)(gp + ug);
                    gz[s] = *(const float2*)(gp + 256 + ug);
                    gn[s] = *(const float2*)(gp + 512 + ug);
                }
            }
        }

        float acc[3][4];
#pragma unroll
        for (int j = 0; j < 3; j++)
#pragma unroll
            for (int q = 0; q < 4; q++) acc[j][q] = 0.f;

        if (t > 0) {
            if (tid < 8) {
                int fv;
                do {
                    asm volatile("ld.acquire.gpu.global.b32 %0, [%1];"
                                 : "=r"(fv) : "l"(flg + (t - 1) * 8 + tid));
                } while (fv == 0);
            }
            __syncthreads();
#pragma unroll
            for (int i = 0; i < 2; i++) {
                const int q = tid + 256 * i;
                const int r = q >> 5;
                const int c8 = (q & 31) * 8;
                float4 v0 = __ldcg((const float4*)(hbase + (size_t)(b0 + r) * HD + c8));
                float4 v1 = __ldcg((const float4*)(hbase + (size_t)(b0 + r) * HD + c8 + 4));
                v0.x = tf32r(v0.x); v0.y = tf32r(v0.y); v0.z = tf32r(v0.z); v0.w = tf32r(v0.w);
                v1.x = tf32r(v1.x); v1.y = tf32r(v1.y); v1.z = tf32r(v1.z); v1.w = tf32r(v1.w);
                *(float4*)&a_s[r * 260 + c8] = v0;
                *(float4*)&a_s[r * 260 + c8 + 4] = v1;
            }
            __syncthreads();

#pragma unroll 4
            for (int kk = 0; kk < 16; kk++) {
                const int cc = kh * 128 + kk * 8 + cb;
                uint32_t a[4];
                a[0] = __float_as_uint(a_s[r0 * 260 + cc]);
                a[1] = __float_as_uint(a_s[(r0 + 8) * 260 + cc]);
                a[2] = __float_as_uint(a_s[r0 * 260 + cc + 4]);
                a[3] = __float_as_uint(a_s[(r0 + 8) * 260 + cc + 4]);
#pragma unroll
                for (int j = 0; j < 3; j++) {
                    const int nn = j * 32 + wlo * 8 + r0;
                    uint32_t bb[2];
                    bb[0] = __float_as_uint(w_s[nn * 260 + cc]);
                    bb[1] = __float_as_uint(w_s[nn * 260 + cc + 4]);
                    mma8(acc[j], a, bb);
                }
            }
        }

        if (warp >= 4) {
            const int idx = (warp - 4) * 32 + lane;
#pragma unroll
            for (int j = 0; j < 3; j++)
#pragma unroll
                for (int q = 0; q < 4; q++) red[idx * 13 + j * 4 + q] = acc[j][q];
        }
        __syncthreads();

        if (warp < 4) {
            const int idx = warp * 32 + lane;
#pragma unroll
            for (int j = 0; j < 3; j++)
#pragma unroll
                for (int q = 0; q < 4; q++) acc[j][q] += red[idx * 13 + j * 4 + q];

            float2* hc[2] = {&hA, &hB};
#pragma unroll
            for (int s = 0; s < 2; s++) {
                const float2 hp = *hc[s];
                float2 hn = hp;
                if (act[s]) {
                    const float rrx = sigma(gr[s].x + acc[0][2 * s]     + bR0);
                    const float rry = sigma(gr[s].y + acc[0][2 * s + 1] + bR1);
                    const float zzx = sigma(gz[s].x + acc[1][2 * s]     + bZ0);
                    const float zzy = sigma(gz[s].y + acc[1][2 * s + 1] + bZ1);
                    const float nnx = tanha(gn[s].x + rrx * (acc[2][2 * s]     + bN0));
                    const float nny = tanha(gn[s].y + rry * (acc[2][2 * s + 1] + bN1));
                    hn.x = (1.f - zzx) * nnx + zzx * hp.x;
                    hn.y = (1.f - zzy) * nny + zzy * hp.y;
                }
                *hc[s] = hn;
                const int b = b0 + r0 + 8 * s;
                *(float2*)(hout + (size_t)b * HD + ug) = hn;
            }
        }

        __syncthreads();
        if (tid == 0) {
            __threadfence();
            *(volatile int*)(flg + t * 8 + gs) = 1;
        }

        if (warp < 4) {
            const float2 hv[2] = {hA, hB};
#pragma unroll
            for (int s = 0; s < 2; s++) {
                if (act[s]) {
                    const int r = r0 + 8 * s;
                    const int b = b0 + r;
                    const float wt = wt_s[r * 128 + posv[s]];
                    float2 cv = {hv[s].x * wt, hv[s].y * wt};
                    *(float2*)(d_ctx + ((size_t)b * L + posv[s]) * H + dir * HD + ug) = cv;
                }
            }
        }
    }
}

// ---- fk2 (tiled) ----
__global__ void __launch_bounds__(256) fk2() {
    extern __shared__ float fsm[];
    float* wc_s = fsm;
    float* ct_s = fsm + 16 * 516;
    const int tid = threadIdx.x;
    const int m0 = blockIdx.x * 128;

    for (int q = tid; q < 2048; q += 256) {
        const int o = q >> 7, c4 = (q & 127) * 4;
        *(float4*)&wc_s[o * 516 + c4] = *(const float4*)(d_Wc + (size_t)o * H + c4);
    }
    __syncthreads();

    const int ml = tid >> 4, o = tid & 15;
    const float tbe = d_tbeff[o];
    for (int c = 0; c < 8; c++) {
        for (int q = tid; q < 2048; q += 256) {
            const int r = q >> 7, c4 = (q & 127) * 4;
            *(float4*)&ct_s[r * 520 + c4] =
                *(const float4*)(d_ctx + (size_t)(m0 + c * 16 + r) * H + c4);
        }
        __syncthreads();
        float acc = 0.f;
#pragma unroll 8
        for (int k4 = 0; k4 < 128; k4++) {
            float4 cv = *(const float4*)&ct_s[ml * 520 + k4 * 4];
            float4 wv = *(const float4*)&wc_s[o * 516 + k4 * 4];
            acc += cv.x * wv.x + cv.y * wv.y + cv.z * wv.z + cv.w * wv.w;
        }
        const int m = m0 + c * 16 + ml;
        d_fk[((size_t)(o >> 2) * ML + m) * T + (o & 3)] = acc + tbe;
        __syncthreads();
    }
}

// ---- CRF marginals ----
__global__ void __launch_bounds__(32) crf_kernel(const int* __restrict__ lens,
                                                 const float* __restrict__ trans) {
    __shared__ float al_s[8 * 516];
    const int tid = threadIdx.x;
    const int tag = tid & 3;
    const int ci  = tid >> 2;
    const int chain = blockIdx.x * 8 + ci;
    const int kb = chain >> 7;
    const int b  = chain & 127;
    const int len = lens[b];
    const unsigned fm = 0xffffffffu;
    const int base = tid & ~3;
    float* al = al_s + ci * 516;

    float tcol[4], trow[4];
#pragma unroll
    for (int i = 0; i < 4; i++) {
        tcol[i] = trans[kb * 16 + i * 4 + tag];
        trow[i] = trans[kb * 16 + tag * 4 + i];
    }
    const float* f = d_fk + ((size_t)kb * ML + (size_t)b * L) * T;

    float alpha = f[tag];
    al[tag] = alpha;
    for (int l = 1; l < L; l++) {
        float a0 = __shfl_sync(fm, alpha, base + 0);
        float a1 = __shfl_sync(fm, alpha, base + 1);
        float a2 = __shfl_sync(fm, alpha, base + 2);
        float a3 = __shfl_sync(fm, alpha, base + 3);
        float na = lse4(a0 + tcol[0], a1 + tcol[1], a2 + tcol[2], a3 + tcol[3]) + f[l * T + tag];
        if (l < len) alpha = na;
        al[l * 4 + tag] = alpha;
    }
    float beta = 0.f, ssum = 0.f;
    float* sp = d_sp + (size_t)(kb * B + b) * L;
    for (int l = L - 1; l >= 0; l--) {
        float v = al[l * 4 + tag] + beta;
        float v0 = __shfl_sync(fm, v, base + 0);
        float v1 = __shfl_sync(fm, v, base + 1);
        float v2 = __shfl_sync(fm, v, base + 2);
        float v3 = __shfl_sync(fm, v, base + 3);
        float p1 = expf(v1 - lse4(v0, v1, v2, v3));
        float spl = (l < len) ? p1 : 0.f;
        ssum += spl;
        if (tag == 0) sp[l] = spl;
        if (l >= 1) {
            float fb = f[l * T + tag] + beta;
            float c0 = __shfl_sync(fm, fb, base + 0);
            float c1 = __shfl_sync(fm, fb, base + 1);
            float c2 = __shfl_sync(fm, fb, base + 2);
            float c3 = __shfl_sync(fm, fb, base + 3);
            float nb2 = lse4(trow[0] + c0, trow[1] + c1, trow[2] + c2, trow[3] + c3);
            if (l < len) beta = nb2;
        }
    }
    if (tag == 0) d_spsum[kb * B + b] = ssum;
}

// ---- pooling + classifier fused ----
__global__ void __launch_bounds__(512) poolcls(const float* __restrict__ lW,
                                               const float* __restrict__ lb) {
    const int b = blockIdx.x, tid = threadIdx.x;
    __shared__ float spn[512];
    __shared__ float red[3][512];
    {
        const int kb = tid >> 7, l = tid & 127;
        spn[tid] = d_sp[(size_t)(kb * B + b) * L + l] / d_spsum[kb * B + b];
    }
    __syncthreads();
    float a0 = 0.f, a1 = 0.f, a2 = 0.f, a3 = 0.f;
    const float* c = d_ctx + (size_t)b * L * H + tid;
    for (int l = 0; l < 128; l++) {
        float cv = c[(size_t)l * H];
        a0 += spn[l] * cv; a1 += spn[128 + l] * cv;
        a2 += spn[256 + l] * cv; a3 += spn[384 + l] * cv;
    }
    float p0 = 0.f, p1 = 0.f, p2 = 0.f, s;
    s = fmaxf(a0, 0.f); p0 += s * lW[tid];        p1 += s * lW[2048 + tid];        p2 += s * lW[4096 + tid];
    s = fmaxf(a1, 0.f); p0 += s * lW[512 + tid];  p1 += s * lW[2560 + tid];        p2 += s * lW[4608 + tid];
    s = fmaxf(a2, 0.f); p0 += s * lW[1024 + tid]; p1 += s * lW[3072 + tid];        p2 += s * lW[5120 + tid];
    s = fmaxf(a3, 0.f); p0 += s * lW[1536 + tid]; p1 += s * lW[3584 + tid];        p2 += s * lW[5632 + tid];
    red[0][tid] = p0; red[1][tid] = p1; red[2][tid] = p2;
    __syncthreads();
    for (int off = 256; off > 0; off >>= 1) {
        if (tid < off) {
            red[0][tid] += red[0][tid + off];
            red[1][tid] += red[1][tid + off];
            red[2][tid] += red[2][tid + off];
        }
        __syncthreads();
    }
    if (tid < 3) d_scores[b * 3 + tid] = red[tid][0] + lb[tid];
}

__global__ void __launch_bounds__(128) loss_kernel(const int* __restrict__ labels,
                                                   float* __restrict__ out) {
    __shared__ float red[128];
    const int b = threadIdx.x;
    float s0 = d_scores[b * 3], s1 = d_scores[b * 3 + 1], s2 = d_scores[b * 3 + 2];
    float m = fmaxf(s0, fmaxf(s1, s2));
    float lse = m + logf(expf(s0 - m) + expf(s1 - m) + expf(s2 - m));
    int lab = labels[b];
    float sl = (lab == 0) ? s0 : ((lab == 1) ? s1 : s2);
    red[b] = lse - sl;
    __syncthreads();
    for (int off = 64; off > 0; off >>= 1) {
        if (b < off) red[b] += red[b + off];
        __syncthreads();
    }
    if (b == 0) out[0] = red[0] / (float)B;
}

extern "C" void kernel_launch(void* const* d_in, const int* in_sizes, int n_in,
                              void* d_out, int out_size) {
    (void)in_sizes; (void)n_in; (void)out_size;
    const float* sents = (const float*)d_in[0];
    const float* mtab  = (const float*)d_in[1];
    const float* gWihf = (const float*)d_in[2];
    const float* gWhhf = (const float*)d_in[3];
    const float* gbihf = (const float*)d_in[4];
    const float* gbhhf = (const float*)d_in[5];
    const float* gWihb = (const float*)d_in[6];
    const float* gWhhb = (const float*)d_in[7];
    const float* gbihb = (const float*)d_in[8];
    const float* gbhhb = (const float*)d_in[9];
    const float* hW    = (const float*)d_in[10];
    const float* hb    = (const float*)d_in[11];
    const float* tW    = (const float*)d_in[12];
    const float* tb    = (const float*)d_in[13];
    const float* trans = (const float*)d_in[14];
    const float* lW    = (const float*)d_in[15];
    const float* lb    = (const float*)d_in[16];
    const int* masks   = (const int*)d_in[17];
    const int* lens    = (const int*)d_in[18];
    const int* labels  = (const int*)d_in[19];
    float* out = (float*)d_out;

    const int smem_gru = (96 * 260 + 16 * 260 + 128 * 13 + 16 * 128) * 4 + 16 * 4;
    cudaFuncSetAttribute(gru_v7, cudaFuncAttributeMaxDynamicSharedMemorySize, smem_gru);
    const int smem_fk = (16 * 516 + 16 * 520) * 4;
    cudaFuncSetAttribute(fk2, cudaFuncAttributeMaxDynamicSharedMemorySize, smem_fk);

    prep_all<<<NB_MAIN + NB_Z, 128>>>(sents, mtab, masks, lens, gWihf, gWihb);  // 1
    prep_small<<<33, 256>>>(hW, tW, hb, tb);                                     // 2
    noop_k<<<1, 32>>>();                                                         // 3
    gemm_gi_bf16<<<dim3(6, 128, 2), 256>>>(gbihf, gbihb);                        // 4 <- ncu
    gru_v7<<<128, 256, smem_gru>>>(lens, gWhhf, gWhhb, gbhhf, gbhhb);            // 5
    fk2<<<128, 256, smem_fk>>>();                                                // 6
    crf_kernel<<<64, 32>>>(lens, trans);                                         // 7
    poolcls<<<B, 512>>>(lW, lb);                                                 // 8
    loss_kernel<<<1, 128>>>(labels, out);                                        // 9
}